// round 2
// baseline (speedup 1.0000x reference)
#include <cuda_runtime.h>
#include <cstdint>
#include <cstddef>

// Problem constants: N=64, T=300, V=25, CIN=COUT=64
#define R_TOT 19200          // N*T rows
#define VC    1600           // V*C
#define NV    25
#define ROWS_B 16            // rows per block in kB
#define GRID_B (R_TOT / ROWS_B)   // 1200
#define TB_E  12             // t-rows per block in kE  (300 = 12*25)

// ---------------- scratch (device globals; no allocations allowed) ----------
__device__ __align__(16) float g_ypre[(size_t)R_TOT * VC];   // 122.88 MB
__device__ __align__(16) float g_Wq[25 * 16 * 64 * 4];       // [v][c4][d][e], e = c%4
__device__ float g_sum[VC];
__device__ float g_sumsq[VC];
__device__ float g_scale[VC];
__device__ float g_shift[VC];

// packed f32x2 FMA (Blackwell): acc.lo += a.lo*b.lo ; acc.hi += a.hi*b.hi
__device__ __forceinline__ void fma2(unsigned long long &acc,
                                     unsigned long long a, unsigned long long b) {
    asm("fma.rn.f32x2 %0, %1, %2, %0;" : "+l"(acc) : "l"(a), "l"(b));
}

// ---------------------------------------------------------------------------
// kA: masked, transposed, c-quad-packed weights + zero the stat accumulators.
// Wq[((v*16 + c4)*64 + d)*4 + e] = W[(4*c4+e)*64 + d] * (tanh(fm[v][4*c4+e]) + 1)
// ---------------------------------------------------------------------------
__global__ void kA(const float* __restrict__ W, const float* __restrict__ fm) {
    int o = blockIdx.x * blockDim.x + threadIdx.x;
    if (o < VC) { g_sum[o] = 0.0f; g_sumsq[o] = 0.0f; }
    if (o >= 25 * 16 * 64 * 4) return;
    int e  = o & 3;
    int d  = (o >> 2) & 63;
    int c4 = (o >> 8) & 15;
    int v  = o >> 12;
    int c  = c4 * 4 + e;
    g_Wq[o] = W[c * 64 + d] * (tanhf(fm[v * 64 + c]) + 1.0f);
}

// ---------------------------------------------------------------------------
// kB: per-row 25x(64x64) masked GEMM.
//   phase 0: stage 16 rows of x0 into shared in gathered layout
//            xg[r][v*64+c] = x0[row][(v+c)%25][c]   (conflict-free scatter)
//   phase 1: warp w handles v in {w, w+8, w+16} (+24 for w==0);
//            lane l accumulates d=l and d=l+32 for all 16 rows with f32x2.
//   epilogue: write ypre, accumulate column sum/sumsq via atomics.
// ---------------------------------------------------------------------------
__global__ void __launch_bounds__(256, 1) kB(const float* __restrict__ x0) {
    extern __shared__ float xg[];            // 16 * 1600 floats = 102400 B
    const int tid  = threadIdx.x;
    const int row0 = blockIdx.x * ROWS_B;

    // ---- phase 0: gather-stage (scalar; bank step = 1 -> conflict free) ----
    int offs[7], fidx[7];
    int cnt = 0;
    for (int f = tid; f < VC; f += 256) {
        int c = f & 63, u = f >> 6;
        int v = (u - c + 75) % 25;
        offs[cnt] = v * 64 + c;
        fidx[cnt] = f;
        cnt++;
    }
    const float* xrow = x0 + (size_t)row0 * VC;
    #pragma unroll 4
    for (int r = 0; r < ROWS_B; r++) {
        const float* xr = xrow + r * VC;
        float* xgr = xg + r * VC;
        #pragma unroll
        for (int j = 0; j < 7; j++) {
            if (j < cnt) xgr[offs[j]] = __ldg(xr + fidx[j]);
        }
    }
    __syncthreads();

    // ---- phase 1: GEMM ----
    const int wid = tid >> 5, lane = tid & 31;
    for (int vi = 0; vi < 4; vi++) {
        int v = wid + vi * 8;
        if (v >= NV) break;                  // only warp 0 reaches vi==3 (v=24)

        unsigned long long accA[ROWS_B], accB[ROWS_B];
        #pragma unroll
        for (int r = 0; r < ROWS_B; r++) { accA[r] = 0ull; accB[r] = 0ull; }

        const ulonglong2* wp = (const ulonglong2*)(g_Wq + (size_t)v * 16 * 64 * 4);
        const float* xbase = xg + v * 64;

        #pragma unroll 4
        for (int c4 = 0; c4 < 16; c4++) {
            ulonglong2 wA = wp[c4 * 64 + lane];        // d = lane,   c = 4c4..4c4+3
            ulonglong2 wB = wp[c4 * 64 + lane + 32];   // d = lane+32
            const float* xb = xbase + c4 * 4;
            #pragma unroll
            for (int r = 0; r < ROWS_B; r++) {
                ulonglong2 xq = *(const ulonglong2*)(xb + r * VC);  // LDS.128 bcast
                fma2(accA[r], xq.x, wA.x);
                fma2(accA[r], xq.y, wA.y);
                fma2(accB[r], xq.x, wB.x);
                fma2(accB[r], xq.y, wB.y);
            }
        }

        // epilogue: combine halves, store ypre, block-partial stats -> atomics
        float sA = 0.f, qA = 0.f, sB = 0.f, qB = 0.f;
        #pragma unroll
        for (int r = 0; r < ROWS_B; r++) {
            float yA = __uint_as_float((unsigned)accA[r]) +
                       __uint_as_float((unsigned)(accA[r] >> 32));
            float yB = __uint_as_float((unsigned)accB[r]) +
                       __uint_as_float((unsigned)(accB[r] >> 32));
            size_t base = (size_t)(row0 + r) * VC + v * 64;
            g_ypre[base + lane]      = yA;
            g_ypre[base + lane + 32] = yB;
            sA += yA; qA += yA * yA;
            sB += yB; qB += yB * yB;
        }
        atomicAdd(&g_sum[v * 64 + lane],        sA);
        atomicAdd(&g_sumsq[v * 64 + lane],      qA);
        atomicAdd(&g_sum[v * 64 + lane + 32],   sB);
        atomicAdd(&g_sumsq[v * 64 + lane + 32], qB);
    }
}

// ---------------------------------------------------------------------------
// kC: fold BN stats (permuted through shift_out) + gamma/beta into per-z-column
//     affine:  z_col j=(v,d) pulls stats from ypre col ((v-d)%25, d).
// ---------------------------------------------------------------------------
__global__ void kC(const float* __restrict__ gamma, const float* __restrict__ beta) {
    int j = blockIdx.x * blockDim.x + threadIdx.x;
    if (j >= VC) return;
    int v = j >> 6, d = j & 63;
    int u = (v - d + 75) % 25;
    int src = u * 64 + d;
    const float inv = 1.0f / 19200.0f;
    float mu  = g_sum[src] * inv;
    float var = g_sumsq[src] * inv - mu * mu;
    float rstd = rsqrtf(var + 1e-5f);
    float sc = rstd * gamma[j];
    g_scale[j] = sc;
    g_shift[j] = beta[j] - mu * sc;
}

// ---------------------------------------------------------------------------
// kE: z = BN(shift_out(ypre)); out[n][d][t][v] = relu(z[t][v][d] + x0[t][v][d])
//   phase 1: scatter BN(ypre) into zs[tt][v*65 + d]   (v = (u+d)%25)
//   phase 2: zs[tt][f + (f>>6)] += x0 flat            (conflict-free)
//   phase 3: transposed read (stride 65 -> bank step 1), relu, coalesced STG
// ---------------------------------------------------------------------------
__global__ void __launch_bounds__(256, 2) kE(const float* __restrict__ x0,
                                             float* __restrict__ out) {
    extern __shared__ float sm[];
    float* zs  = sm;                    // TB_E * 1625
    float* ssc = sm + TB_E * 1625;      // 1600
    float* ssh = ssc + VC;              // 1600
    const int tid = threadIdx.x;
    const int t0  = blockIdx.x * TB_E;
    const int n   = blockIdx.y;

    for (int j = tid; j < VC; j += 256) { ssc[j] = g_scale[j]; ssh[j] = g_shift[j]; }

    // per-thread precomputed offsets (same for every tt)
    int f_l[7], zo_l[7], jo_l[7];
    int cnt = 0;
    for (int f = tid; f < VC; f += 256) {
        int d = f & 63, u = f >> 6;
        int v = (u + d) % 25;
        f_l[cnt]  = f;
        zo_l[cnt] = v * 65 + d;
        jo_l[cnt] = v * 64 + d;
        cnt++;
    }
    __syncthreads();

    const size_t rowbase = ((size_t)n * 300 + t0) * VC;

    // phase 1: BN + shift_out scatter
    for (int tt = 0; tt < TB_E; tt++) {
        const float* yr = g_ypre + rowbase + (size_t)tt * VC;
        float* zrow = zs + tt * 1625;
        #pragma unroll
        for (int j = 0; j < 7; j++) {
            if (j < cnt) {
                float y = __ldg(yr + f_l[j]);
                zrow[zo_l[j]] = y * ssc[jo_l[j]] + ssh[jo_l[j]];
            }
        }
    }
    __syncthreads();

    // phase 2: add shortcut (x0 flat -> padded slot f + u)
    for (int tt = 0; tt < TB_E; tt++) {
        const float* xr = x0 + rowbase + (size_t)tt * VC;
        float* zrow = zs + tt * 1625;
        for (int f = tid; f < VC; f += 256) {
            zrow[f + (f >> 6)] += __ldg(xr + f);
        }
    }
    __syncthreads();

    // phase 3: relu + transpose to (n, d, t, v), coalesced stores
    const size_t obase0 = ((size_t)n * R_TOT + t0) * 25;   // n*480000 + t0*25
    for (int d = 0; d < 64; d++) {
        size_t obase = obase0 + (size_t)d * 7500;
        for (int i = tid; i < TB_E * 25; i += 256) {
            int tt = i / 25;
            int v  = i - tt * 25;
            out[obase + i] = fmaxf(zs[tt * 1625 + v * 65 + d], 0.0f);
        }
    }
}

// ---------------------------------------------------------------------------
extern "C" void kernel_launch(void* const* d_in, const int* in_sizes, int n_in,
                              void* d_out, int out_size) {
    const float* x0    = (const float*)d_in[0];
    const float* W     = (const float*)d_in[1];
    // d_in[2] = b : provably cancelled by BatchNorm -> unused
    const float* fm    = (const float*)d_in[3];
    const float* gamma = (const float*)d_in[4];
    const float* beta  = (const float*)d_in[5];
    float* out = (float*)d_out;

    const int smemB = ROWS_B * VC * 4;                 // 102400
    const int smemE = (TB_E * 1625 + 2 * VC) * 4;      // 90800

    cudaFuncSetAttribute(kB, cudaFuncAttributeMaxDynamicSharedMemorySize, smemB);
    cudaFuncSetAttribute(kE, cudaFuncAttributeMaxDynamicSharedMemorySize, smemE);

    kA<<<400, 256>>>(W, fm);
    kB<<<GRID_B, 256, smemB>>>(x0);
    kC<<<7, 256>>>(gamma, beta);
    dim3 gE(300 / TB_E, 64);
    kE<<<gE, 256, smemE>>>(x0, out);
}

// round 5
// speedup vs baseline: 2.3450x; 2.3450x over previous
#include <cuda_runtime.h>
#include <cstdint>
#include <cstddef>

// Problem constants: N=64, T=300, V=25, CIN=COUT=64
#define R_TOT 19200          // N*T rows
#define VC    1600           // V*C
#define NV    25
#define ROWS_B 8             // rows per block in kB
#define GRID_B (R_TOT / ROWS_B)   // 2400
#define TB_E  4              // t-rows per block in kE  (300 = 75*4)

// ---------------- scratch (device globals; no allocations allowed) ----------
__device__ __align__(16) float g_ypre[(size_t)R_TOT * VC];   // 122.88 MB
__device__ __align__(16) float g_Wq[25 * 16 * 64 * 4];       // [v][c4][d][e], e = c%4
__device__ float g_sum[VC];
__device__ float g_sumsq[VC];
__device__ __align__(16) float g_scale[VC];
__device__ __align__(16) float g_shift[VC];

// packed f32x2 FMA (Blackwell): acc.lo += a.lo*b.lo ; acc.hi += a.hi*b.hi
__device__ __forceinline__ void fma2(unsigned long long &acc,
                                     unsigned long long a, unsigned long long b) {
    asm("fma.rn.f32x2 %0, %1, %2, %0;" : "+l"(acc) : "l"(a), "l"(b));
}

// ---------------------------------------------------------------------------
// kA: masked, transposed, c-quad-packed weights + zero the stat accumulators.
// Wq[((v*16 + c4)*64 + d)*4 + e] = W[(4*c4+e)*64 + d] * (tanh(fm[v][4*c4+e]) + 1)
// ---------------------------------------------------------------------------
__global__ void kA(const float* __restrict__ W, const float* __restrict__ fm) {
    int o = blockIdx.x * blockDim.x + threadIdx.x;
    if (o < VC) { g_sum[o] = 0.0f; g_sumsq[o] = 0.0f; }
    if (o >= 25 * 16 * 64 * 4) return;
    int e  = o & 3;
    int d  = (o >> 2) & 63;
    int c4 = (o >> 8) & 15;
    int v  = o >> 12;
    int c  = c4 * 4 + e;
    g_Wq[o] = W[c * 64 + d] * (tanhf(fm[v * 64 + c]) + 1.0f);
}

// ---------------------------------------------------------------------------
// kB: per-row 25x(64x64) masked GEMM (fp32, packed f32x2 FFMA).
//   phase 0: stage 8 rows of x0 into shared in shift_in-gathered layout
//            xg[r][v*64+c] = x0[row][(v+c)%25][c]   (float4 LDG, scalar STS)
//   phase 1: 4 warps; warp w handles v = w + 4k; lane owns d=l and d=l+32,
//            8-row f32x2 accumulators.
//   epilogue: write ypre, accumulate column sum/sumsq via atomics (REDG).
// ---------------------------------------------------------------------------
__global__ void __launch_bounds__(128, 4) kB(const float* __restrict__ x0) {
    extern __shared__ float xg[];            // 8 * 1600 floats = 51200 B
    const int tid  = threadIdx.x;
    const int row0 = blockIdx.x * ROWS_B;

    // ---- phase 0: gathered staging ----
    // per-thread float4 chunks: q = tid + j*128, q < 400  (f = 4q)
    int qf[4];                // global float4 index
    int slt[4][4];            // smem scatter slots for the 4 scalars
    int cnt = 0;
    for (int q = tid; q < 400; q += 128) {
        int c0 = (q * 4) & 63;
        int u  = q >> 4;
        qf[cnt] = q;
        #pragma unroll
        for (int s = 0; s < 4; s++) {
            int c = c0 + s;
            int v = (u - c + 75) % 25;
            slt[cnt][s] = v * 64 + c;
        }
        cnt++;
    }
    const float4* xrow = (const float4*)(x0 + (size_t)row0 * VC);
    #pragma unroll
    for (int r = 0; r < ROWS_B; r++) {
        const float4* xr = xrow + r * 400;
        float* xgr = xg + r * VC;
        #pragma unroll
        for (int j = 0; j < 4; j++) {
            if (j < cnt) {
                float4 val = __ldg(xr + qf[j]);
                xgr[slt[j][0]] = val.x;
                xgr[slt[j][1]] = val.y;
                xgr[slt[j][2]] = val.z;
                xgr[slt[j][3]] = val.w;
            }
        }
    }
    __syncthreads();

    // ---- phase 1: GEMM ----
    const int wid = tid >> 5, lane = tid & 31;
    for (int k = 0; k < 7; k++) {
        int v = wid + k * 4;
        if (v >= NV) break;                  // only warp 0 reaches k==6 (v=24)

        unsigned long long accA[ROWS_B], accB[ROWS_B];
        #pragma unroll
        for (int r = 0; r < ROWS_B; r++) { accA[r] = 0ull; accB[r] = 0ull; }

        const ulonglong2* wp = (const ulonglong2*)(g_Wq + (size_t)v * 16 * 64 * 4);
        const float* xbase = xg + v * 64;

        #pragma unroll 4
        for (int c4 = 0; c4 < 16; c4++) {
            ulonglong2 wA = __ldg(wp + c4 * 64 + lane);      // d = lane
            ulonglong2 wB = __ldg(wp + c4 * 64 + lane + 32); // d = lane+32
            const float* xb = xbase + c4 * 4;
            #pragma unroll
            for (int r = 0; r < ROWS_B; r++) {
                ulonglong2 xq = *(const ulonglong2*)(xb + r * VC);  // LDS.128 bcast
                fma2(accA[r], xq.x, wA.x);
                fma2(accA[r], xq.y, wA.y);
                fma2(accB[r], xq.x, wB.x);
                fma2(accB[r], xq.y, wB.y);
            }
        }

        // epilogue: combine halves, store ypre, block-partial stats -> atomics
        float sA = 0.f, qA = 0.f, sB = 0.f, qB = 0.f;
        #pragma unroll
        for (int r = 0; r < ROWS_B; r++) {
            float yA = __uint_as_float((unsigned)accA[r]) +
                       __uint_as_float((unsigned)(accA[r] >> 32));
            float yB = __uint_as_float((unsigned)accB[r]) +
                       __uint_as_float((unsigned)(accB[r] >> 32));
            size_t base = (size_t)(row0 + r) * VC + v * 64;
            g_ypre[base + lane]      = yA;
            g_ypre[base + lane + 32] = yB;
            sA += yA; qA += yA * yA;
            sB += yB; qB += yB * yB;
        }
        atomicAdd(&g_sum[v * 64 + lane],        sA);
        atomicAdd(&g_sumsq[v * 64 + lane],      qA);
        atomicAdd(&g_sum[v * 64 + lane + 32],   sB);
        atomicAdd(&g_sumsq[v * 64 + lane + 32], qB);
    }
}

// ---------------------------------------------------------------------------
// kC: fold BN stats (permuted through shift_out) + gamma/beta into per-z-column
//     affine:  z_col j=(v,d) pulls stats from ypre col ((v-d)%25, d).
//     NOTE: input bias b is provably cancelled by BN (constant per column).
// ---------------------------------------------------------------------------
__global__ void kC(const float* __restrict__ gamma, const float* __restrict__ beta) {
    int j = blockIdx.x * blockDim.x + threadIdx.x;
    if (j >= VC) return;
    int v = j >> 6, d = j & 63;
    int u = (v - d + 75) % 25;
    int src = u * 64 + d;
    const float inv = 1.0f / 19200.0f;
    float mu  = g_sum[src] * inv;
    float var = g_sumsq[src] * inv - mu * mu;
    float rstd = rsqrtf(var + 1e-5f);
    float sc = rstd * gamma[j];
    g_scale[j] = sc;
    g_shift[j] = beta[j] - mu * sc;
}

// ---------------------------------------------------------------------------
// kE: z = BN(shift_out(ypre)) + x0 ; out[n][d][t][v] = relu(z), transposed.
//   p1: raw scatter  zs[tt][((u+d)%25)*65 + d] = ypre[row][u*64+d]  (float4 LDG)
//   p2: shared RMW   zs[f+(f>>6)] = zs*ssc[f] + ssh[f] + x0[f]      (all coalesced)
//   p3: transposed read (stride 65 -> conflict-lite), relu, float4 STG
// ---------------------------------------------------------------------------
__global__ void __launch_bounds__(256) kE(const float* __restrict__ x0,
                                          float* __restrict__ out) {
    extern __shared__ float sm[];
    float* zs  = sm;                    // TB_E * 1625 = 6500 floats
    float* ssc = sm + TB_E * 1625;      // 1600
    float* ssh = ssc + VC;              // 1600
    const int tid = threadIdx.x;
    const int t0  = blockIdx.x * TB_E;
    const int n   = blockIdx.y;

    // load BN affine tables (coalesced float4)
    for (int q = tid; q < 400; q += 256) {
        ((float4*)ssc)[q] = __ldg((const float4*)g_scale + q);
        ((float4*)ssh)[q] = __ldg((const float4*)g_shift + q);
    }

    // per-thread scatter slots for p1 (same for every tt)
    int qf[2], pslt[2][4];
    int cnt = 0;
    for (int q = tid; q < 400; q += 256) {
        int d0 = (q * 4) & 63;
        int u  = q >> 4;
        qf[cnt] = q;
        #pragma unroll
        for (int s = 0; s < 4; s++) {
            int d = d0 + s;
            int v = (u + d) % 25;
            pslt[cnt][s] = v * 65 + d;
        }
        cnt++;
    }
    __syncthreads();   // covers table load

    const size_t rowbase = ((size_t)n * 300 + t0) * VC;

    // p1: raw ypre scatter into padded shift_out layout
    #pragma unroll
    for (int tt = 0; tt < TB_E; tt++) {
        const float4* yr = (const float4*)(g_ypre + rowbase + (size_t)tt * VC);
        float* zrow = zs + tt * 1625;
        #pragma unroll
        for (int j = 0; j < 2; j++) {
            if (j < cnt) {
                float4 y = __ldg(yr + qf[j]);
                zrow[pslt[j][0]] = y.x;
                zrow[pslt[j][1]] = y.y;
                zrow[pslt[j][2]] = y.z;
                zrow[pslt[j][3]] = y.w;
            }
        }
    }
    __syncthreads();

    // p2: BN + shortcut, everything coalesced at output-flat f
    #pragma unroll
    for (int tt = 0; tt < TB_E; tt++) {
        const float4* xr = (const float4*)(x0 + rowbase + (size_t)tt * VC);
        float* zrow = zs + tt * 1625;
        for (int q = tid; q < 400; q += 256) {
            float4 xv = __ldg(xr + q);
            float4 sc = ((const float4*)ssc)[q];
            float4 sh = ((const float4*)ssh)[q];
            int f = q * 4;
            int slot = f + (f >> 6);     // f..f+3 same v -> consecutive slots
            zrow[slot + 0] = zrow[slot + 0] * sc.x + sh.x + xv.x;
            zrow[slot + 1] = zrow[slot + 1] * sc.y + sh.y + xv.y;
            zrow[slot + 2] = zrow[slot + 2] * sc.z + sh.z + xv.z;
            zrow[slot + 3] = zrow[slot + 3] * sc.w + sh.w + xv.w;
        }
    }
    __syncthreads();

    // p3: relu + transpose to (n, d, t, v), float4 coalesced stores
    // output elems per block = 64 * TB_E * 25 = 6400 -> 1600 float4
    const size_t obase0 = ((size_t)n * R_TOT + t0) * 25;   // n*480000 + t0*25
    for (int i4 = tid; i4 < 1600; i4 += 256) {
        int i = i4 * 4;
        int d = i / 100;               // fixed across the 4 scalars (100 % 4 == 0)
        int rem = i - d * 100;         // 0..96
        float4 o;
        {
            int tt = rem / 25, v = rem - tt * 25;
            o.x = fmaxf(zs[tt * 1625 + v * 65 + d], 0.0f);
        }
        {
            int r1 = rem + 1; int tt = r1 / 25, v = r1 - tt * 25;
            o.y = fmaxf(zs[tt * 1625 + v * 65 + d], 0.0f);
        }
        {
            int r2 = rem + 2; int tt = r2 / 25, v = r2 - tt * 25;
            o.z = fmaxf(zs[tt * 1625 + v * 65 + d], 0.0f);
        }
        {
            int r3 = rem + 3; int tt = r3 / 25, v = r3 - tt * 25;
            o.w = fmaxf(zs[tt * 1625 + v * 65 + d], 0.0f);
        }
        *(float4*)(out + obase0 + (size_t)d * 7500 + rem) = o;
    }
}

// ---------------------------------------------------------------------------
extern "C" void kernel_launch(void* const* d_in, const int* in_sizes, int n_in,
                              void* d_out, int out_size) {
    const float* x0    = (const float*)d_in[0];
    const float* W     = (const float*)d_in[1];
    // d_in[2] = b : cancelled by BatchNorm -> unused
    const float* fm    = (const float*)d_in[3];
    const float* gamma = (const float*)d_in[4];
    const float* beta  = (const float*)d_in[5];
    float* out = (float*)d_out;

    const int smemB = ROWS_B * VC * 4;                 // 51200
    const int smemE = (TB_E * 1625 + 2 * VC) * 4;      // 38800

    cudaFuncSetAttribute(kB, cudaFuncAttributeMaxDynamicSharedMemorySize, smemB);
    cudaFuncSetAttribute(kE, cudaFuncAttributeMaxDynamicSharedMemorySize, smemE);

    kA<<<400, 256>>>(W, fm);
    kB<<<GRID_B, 128, smemB>>>(x0);
    kC<<<7, 256>>>(gamma, beta);
    dim3 gE(300 / TB_E, 64);
    kE<<<gE, 256, smemE>>>(x0, out);
}